// round 9
// baseline (speedup 1.0000x reference)
#include <cuda_runtime.h>

// ---------------------------------------------------------------------------
// TemporalGNN: 2x TransformerConv(heads=1), N=100k nodes, E=800k edges, C=128.
// CSR-by-dst build + per-layer [tf32 tensor-core gemm4] -> [fused attention].
// R8 = R7 attention (8-lanes/edge x 4-edges/iter) + GEMM K-loop register
// prefetch (global-load latency hidden under the MMA phase).
// ---------------------------------------------------------------------------

#define NN 100000
#define NE 800000
#define C  128
#define CHUNK 1024
#define NBLK ((NN + CHUNK - 1) / CHUNK)  // 98

__device__ float    g_q[NN * C];
__device__ float    g_k[NN * C];
__device__ float    g_v[NN * C];
__device__ float    g_s[NN * C];
__device__ float    g_h[NN * C];
__device__ unsigned g_wt[8 * C * C];   // all 8 weight mats, transposed, tf32 bits
__device__ int      g_deg[NN];
__device__ int      g_rptmp[NN + 1];
__device__ int      g_rowptr[NN + 1];
__device__ int      g_wpos[NN];
__device__ int      g_blocksums[NBLK];
__device__ int      g_blockoffs[NBLK];
__device__ int      g_srcs[NE];
__device__ int      g_is_i32;

struct WPtrs  { const float* W[8]; };
struct BiasPtrs { const float* b[4]; };

__device__ __forceinline__ unsigned f2tf32(float x) {
    unsigned u;
    asm("cvt.rna.tf32.f32 %0, %1;" : "=r"(u) : "f"(x));
    return u;
}

__device__ __forceinline__ void mma_tf32(float* c, const unsigned* a, const unsigned* b) {
    asm volatile(
        "mma.sync.aligned.m16n8k8.row.col.f32.tf32.tf32.f32 "
        "{%0,%1,%2,%3}, {%4,%5,%6,%7}, {%8,%9}, {%0,%1,%2,%3};"
        : "+f"(c[0]), "+f"(c[1]), "+f"(c[2]), "+f"(c[3])
        : "r"(a[0]), "r"(a[1]), "r"(a[2]), "r"(a[3]), "r"(b[0]), "r"(b[1]));
}

// ---------------------------------------------------------------------------
// edge_index dtype detection (int32 vs int64): int64 values < 2^31 have all
// odd 32-bit words zero.
// ---------------------------------------------------------------------------
__global__ void detect_kernel(const int* __restrict__ ei32) {
    __shared__ int found;
    if (threadIdx.x == 0) found = 0;
    __syncthreads();
    for (int i = threadIdx.x; i < 4096; i += blockDim.x)
        if (ei32[2 * i + 1] != 0) found = 1;
    __syncthreads();
    if (threadIdx.x == 0) g_is_i32 = found;
}

__device__ __forceinline__ int load_src(const void* ei, int e) {
    if (g_is_i32) return ((const int*)ei)[e];
    return (int)((const long long*)ei)[e];
}
__device__ __forceinline__ int load_dst(const void* ei, int e) {
    if (g_is_i32) return ((const int*)ei)[NE + e];
    return (int)((const long long*)ei)[NE + e];
}

// ---------------------------------------------------------------------------
// CSR build
// ---------------------------------------------------------------------------
__global__ void deg_zero_kernel() {
    int i = blockIdx.x * blockDim.x + threadIdx.x;
    if (i < NN) g_deg[i] = 0;
}

__global__ void hist_kernel(const void* __restrict__ ei) {
    int e = blockIdx.x * blockDim.x + threadIdx.x;
    if (e >= NE) return;
    int d = load_dst(ei, e);
    int s = load_src(ei, e);
    if ((unsigned)d < NN && (unsigned)s < NN) atomicAdd(&g_deg[d], 1);
}

__global__ __launch_bounds__(CHUNK) void scan1_kernel() {
    __shared__ int sh[CHUNK];
    int t = threadIdx.x;
    int i = blockIdx.x * CHUNK + t;
    int v = (i < NN) ? g_deg[i] : 0;
    sh[t] = v;
    __syncthreads();
#pragma unroll
    for (int off = 1; off < CHUNK; off <<= 1) {
        int add = (t >= off) ? sh[t - off] : 0;
        __syncthreads();
        sh[t] += add;
        __syncthreads();
    }
    if (i < NN) g_rptmp[i + 1] = sh[t];
    if (t == CHUNK - 1) g_blocksums[blockIdx.x] = sh[t];
}

__global__ __launch_bounds__(128) void scan2_kernel() {
    __shared__ int sh[128];
    int t = threadIdx.x;
    int v = (t < NBLK) ? g_blocksums[t] : 0;
    sh[t] = v;
    __syncthreads();
#pragma unroll
    for (int off = 1; off < 128; off <<= 1) {
        int add = (t >= off) ? sh[t - off] : 0;
        __syncthreads();
        sh[t] += add;
        __syncthreads();
    }
    if (t < NBLK) g_blockoffs[t] = sh[t] - v;
}

__global__ void scan3_kernel() {
    int i = blockIdx.x * blockDim.x + threadIdx.x;
    if (i >= NN) return;
    g_rowptr[i + 1] = g_rptmp[i + 1] + g_blockoffs[i >> 10];
    g_wpos[i] = (i == 0) ? 0 : g_rptmp[i] + g_blockoffs[(i - 1) >> 10];
    if (i == 0) g_rowptr[0] = 0;
}

__global__ void scatter_kernel(const void* __restrict__ ei) {
    int e = blockIdx.x * blockDim.x + threadIdx.x;
    if (e >= NE) return;
    int d = load_dst(ei, e);
    int s = load_src(ei, e);
    if ((unsigned)d >= NN || (unsigned)s >= NN) return;
    int pos = atomicAdd(&g_wpos[d], 1);
    g_srcs[pos] = s;
}

// ---------------------------------------------------------------------------
// Weight prep: transpose W[k][n] -> Wt[n][k] with round-to-nearest tf32.
// ---------------------------------------------------------------------------
__global__ void wprep_kernel(WPtrs wp) {
    int mat = blockIdx.y;
    int idx = blockIdx.x * blockDim.x + threadIdx.x;
    if (idx >= C * C) return;
    int k = idx >> 7;
    int n = idx & 127;
    g_wt[mat * C * C + n * C + k] = f2tf32(wp.W[mat][idx]);
}

// ---------------------------------------------------------------------------
// tf32 tensor-core GEMM: {g_q,g_k,g_v,g_s}[mat] = X @ W_mat + b_mat
// BM=128, BN=128, BK=32. 256 threads = 8 warps, warp tile 64x32.
// R8: K-loop register prefetch — next tile's global loads issue right after
// the post-store sync and retire during the MMA phase. OOB rows are clamped
// to row 0 (results for those rows are never stored; a-frag rows map 1:1 to
// output rows, so no valid output depends on them).
// ---------------------------------------------------------------------------
__global__ __launch_bounds__(256) void gemm4_tc(const float* __restrict__ Xin,
                                                BiasPtrs bp, int use_h, int wt_base) {
    const int mat = blockIdx.y;
    const float* __restrict__ X = use_h ? g_h : Xin;
    const float* __restrict__ bias = bp.b[mat];
    float* outs[4] = {g_q, g_k, g_v, g_s};
    float* __restrict__ Y = outs[mat];
    const unsigned* __restrict__ Wt = &g_wt[(wt_base + mat) * C * C];

    __shared__ unsigned Xs[128][36];
    __shared__ unsigned Ws[128][36];

    const int tid = threadIdx.x;
    const int lane = tid & 31;
    const int wid = tid >> 5;
    const int warp_m = (wid & 1) * 64;
    const int warp_n = (wid >> 1) * 32;
    const int blockRow = blockIdx.x * 128;

    const int lrow = tid >> 1;           // 0..127
    const int lcol = (tid & 1) * 16;     // 0 or 16

    const int gr = blockRow + lrow;
    const int grc = (gr < NN) ? gr : 0;  // clamp OOB rows (never stored)
    const float* __restrict__ xrow = &X[grc * 128];
    const unsigned* __restrict__ wrow = &Wt[lrow * 128];

    float acc[4][4][4];
#pragma unroll
    for (int mi = 0; mi < 4; mi++)
#pragma unroll
        for (int ni = 0; ni < 4; ni++)
#pragma unroll
            for (int r = 0; r < 4; r++) acc[mi][ni][r] = 0.0f;

    float4 xr[4];
    uint4  wr[4];
#pragma unroll
    for (int j = 0; j < 4; j++) {
        xr[j] = *(const float4*)&xrow[lcol + j * 4];
        wr[j] = *(const uint4*)&wrow[lcol + j * 4];
    }

#pragma unroll
    for (int it = 0; it < 4; it++) {
        // store current tile (X converted to tf32 at store)
#pragma unroll
        for (int j = 0; j < 4; j++) {
            const int c = lcol + j * 4;
            uint4 uv;
            uv.x = f2tf32(xr[j].x); uv.y = f2tf32(xr[j].y);
            uv.z = f2tf32(xr[j].z); uv.w = f2tf32(xr[j].w);
            *(uint4*)&Xs[lrow][c] = uv;
            *(uint4*)&Ws[lrow][c] = wr[j];
        }
        __syncthreads();

        // prefetch next tile (retires under the MMA phase)
        if (it < 3) {
            const int nk0 = (it + 1) * 32;
#pragma unroll
            for (int j = 0; j < 4; j++) {
                xr[j] = *(const float4*)&xrow[nk0 + lcol + j * 4];
                wr[j] = *(const uint4*)&wrow[nk0 + lcol + j * 4];
            }
        }

#pragma unroll
        for (int kk = 0; kk < 32; kk += 8) {
            unsigned a[4][4], b[4][2];
#pragma unroll
            for (int mi = 0; mi < 4; mi++) {
                const int r = warp_m + mi * 16 + (lane >> 2);
                const int kc = kk + (lane & 3);
                a[mi][0] = Xs[r][kc];
                a[mi][1] = Xs[r + 8][kc];
                a[mi][2] = Xs[r][kc + 4];
                a[mi][3] = Xs[r + 8][kc + 4];
            }
#pragma unroll
            for (int ni = 0; ni < 4; ni++) {
                const int n = warp_n + ni * 8 + (lane >> 2);
                const int kc = kk + (lane & 3);
                b[ni][0] = Ws[n][kc];
                b[ni][1] = Ws[n][kc + 4];
            }
#pragma unroll
            for (int mi = 0; mi < 4; mi++)
#pragma unroll
                for (int ni = 0; ni < 4; ni++) mma_tf32(acc[mi][ni], a[mi], b[ni]);
        }
        __syncthreads();
    }

    float2 b2[4];
#pragma unroll
    for (int ni = 0; ni < 4; ni++)
        b2[ni] = *(const float2*)&bias[warp_n + ni * 8 + (lane & 3) * 2];

#pragma unroll
    for (int mi = 0; mi < 4; mi++) {
        const int row0 = blockRow + warp_m + mi * 16 + (lane >> 2);
        const int row1 = row0 + 8;
#pragma unroll
        for (int ni = 0; ni < 4; ni++) {
            const int col = warp_n + ni * 8 + (lane & 3) * 2;
            if (row0 < NN) {
                float2 r;
                r.x = acc[mi][ni][0] + b2[ni].x;
                r.y = acc[mi][ni][1] + b2[ni].y;
                *(float2*)&Y[row0 * 128 + col] = r;
            }
            if (row1 < NN) {
                float2 r;
                r.x = acc[mi][ni][2] + b2[ni].x;
                r.y = acc[mi][ni][3] + b2[ni].y;
                *(float2*)&Y[row1 * 128 + col] = r;
            }
        }
    }
}

// ---------------------------------------------------------------------------
// Fused attention (R7): one warp per dst node; 4 edge groups of 8 lanes.
// Group g handles edge base+g; sublane sl owns channels [16*sl, 16*sl+16).
//   p_partial = <q_sl, k_sl>;  3-level shfl (xor 1,2,4) sums within group.
//   w = exp(p/sqrt(128)) (0 for tail-invalid groups; their loads clamp to
//   src 0 -> L1-resident, ~free).
//   Final: xor 8,16 combines the 4 groups' esum/acc; g==0 lanes write
//   out = acc/esum + skip (+relu).
// ---------------------------------------------------------------------------
__global__ __launch_bounds__(256) void attn_kernel(float* __restrict__ outp,
                                                   int relu, int write_h) {
    const int node = (blockIdx.x * blockDim.x + threadIdx.x) >> 5;
    const int lane = threadIdx.x & 31;
    if (node >= NN) return;

    float* __restrict__ out = write_h ? g_h : outp;

    const int g  = lane >> 3;   // edge group 0..3
    const int sl = lane & 7;    // sublane: channels [16*sl, 16*sl+16)

    const int beg = g_rowptr[node];
    const int end = g_rowptr[node + 1];

    const float4* __restrict__ qrow = (const float4*)&g_q[node * C];
    float4 q0 = qrow[sl * 4 + 0];
    float4 q1 = qrow[sl * 4 + 1];
    float4 q2 = qrow[sl * 4 + 2];
    float4 q3 = qrow[sl * 4 + 3];

    float4 a0 = make_float4(0.f, 0.f, 0.f, 0.f);
    float4 a1 = a0, a2 = a0, a3 = a0;
    float esum = 0.f;

    for (int base = beg; base < end; base += 4) {
        const int ei = base + g;
        const bool valid = (ei < end);
        const int src = valid ? g_srcs[ei] : 0;

        const float4* __restrict__ krow = (const float4*)&g_k[src * C];
        const float4 k0 = krow[sl * 4 + 0];
        const float4 k1 = krow[sl * 4 + 1];
        const float4 k2 = krow[sl * 4 + 2];
        const float4 k3 = krow[sl * 4 + 3];
        const float4* __restrict__ vrow = (const float4*)&g_v[src * C];
        const float4 v0 = vrow[sl * 4 + 0];
        const float4 v1 = vrow[sl * 4 + 1];
        const float4 v2 = vrow[sl * 4 + 2];
        const float4 v3 = vrow[sl * 4 + 3];

        float p = q0.x * k0.x + q0.y * k0.y + q0.z * k0.z + q0.w * k0.w;
        p = fmaf(q1.x, k1.x, p); p = fmaf(q1.y, k1.y, p);
        p = fmaf(q1.z, k1.z, p); p = fmaf(q1.w, k1.w, p);
        p = fmaf(q2.x, k2.x, p); p = fmaf(q2.y, k2.y, p);
        p = fmaf(q2.z, k2.z, p); p = fmaf(q2.w, k2.w, p);
        p = fmaf(q3.x, k3.x, p); p = fmaf(q3.y, k3.y, p);
        p = fmaf(q3.z, k3.z, p); p = fmaf(q3.w, k3.w, p);

        // reduce within the 8-lane group (xor 1,2,4 stays inside the group)
        p += __shfl_xor_sync(0xFFFFFFFFu, p, 1);
        p += __shfl_xor_sync(0xFFFFFFFFu, p, 2);
        p += __shfl_xor_sync(0xFFFFFFFFu, p, 4);

        const float w = valid ? __expf(p * 0.08838834764831845f) : 0.f;
        esum += w;

        a0.x = fmaf(w, v0.x, a0.x); a0.y = fmaf(w, v0.y, a0.y);
        a0.z = fmaf(w, v0.z, a0.z); a0.w = fmaf(w, v0.w, a0.w);
        a1.x = fmaf(w, v1.x, a1.x); a1.y = fmaf(w, v1.y, a1.y);
        a1.z = fmaf(w, v1.z, a1.z); a1.w = fmaf(w, v1.w, a1.w);
        a2.x = fmaf(w, v2.x, a2.x); a2.y = fmaf(w, v2.y, a2.y);
        a2.z = fmaf(w, v2.z, a2.z); a2.w = fmaf(w, v2.w, a2.w);
        a3.x = fmaf(w, v3.x, a3.x); a3.y = fmaf(w, v3.y, a3.y);
        a3.z = fmaf(w, v3.z, a3.z); a3.w = fmaf(w, v3.w, a3.w);
    }

    // combine the 4 edge groups (xor 8, 16 flip the group bits)
#pragma unroll
    for (int off = 8; off <= 16; off <<= 1) {
        esum += __shfl_xor_sync(0xFFFFFFFFu, esum, off);
        a0.x += __shfl_xor_sync(0xFFFFFFFFu, a0.x, off);
        a0.y += __shfl_xor_sync(0xFFFFFFFFu, a0.y, off);
        a0.z += __shfl_xor_sync(0xFFFFFFFFu, a0.z, off);
        a0.w += __shfl_xor_sync(0xFFFFFFFFu, a0.w, off);
        a1.x += __shfl_xor_sync(0xFFFFFFFFu, a1.x, off);
        a1.y += __shfl_xor_sync(0xFFFFFFFFu, a1.y, off);
        a1.z += __shfl_xor_sync(0xFFFFFFFFu, a1.z, off);
        a1.w += __shfl_xor_sync(0xFFFFFFFFu, a1.w, off);
        a2.x += __shfl_xor_sync(0xFFFFFFFFu, a2.x, off);
        a2.y += __shfl_xor_sync(0xFFFFFFFFu, a2.y, off);
        a2.z += __shfl_xor_sync(0xFFFFFFFFu, a2.z, off);
        a2.w += __shfl_xor_sync(0xFFFFFFFFu, a2.w, off);
        a3.x += __shfl_xor_sync(0xFFFFFFFFu, a3.x, off);
        a3.y += __shfl_xor_sync(0xFFFFFFFFu, a3.y, off);
        a3.z += __shfl_xor_sync(0xFFFFFFFFu, a3.z, off);
        a3.w += __shfl_xor_sync(0xFFFFFFFFu, a3.w, off);
    }

    if (g == 0) {
        const float inv = (esum > 0.f) ? (1.0f / esum) : 0.f;
        const int base = node * C + sl * 16;
        const float4* __restrict__ srow = (const float4*)&g_s[base];
        float4 av[4] = {a0, a1, a2, a3};
#pragma unroll
        for (int j = 0; j < 4; j++) {
            const float4 s4 = srow[j];
            float4 r;
            r.x = fmaf(av[j].x, inv, s4.x);
            r.y = fmaf(av[j].y, inv, s4.y);
            r.z = fmaf(av[j].z, inv, s4.z);
            r.w = fmaf(av[j].w, inv, s4.w);
            if (relu) {
                r.x = fmaxf(r.x, 0.f); r.y = fmaxf(r.y, 0.f);
                r.z = fmaxf(r.z, 0.f); r.w = fmaxf(r.w, 0.f);
            }
            *(float4*)&out[base + j * 4] = r;
        }
    }
}

// ---------------------------------------------------------------------------
// Launch (pure kernel launches — graph-capture safe)
// ---------------------------------------------------------------------------
extern "C" void kernel_launch(void* const* d_in, const int* in_sizes, int n_in,
                              void* d_out, int out_size) {
    const float* x = (const float*)d_in[0];
    const void* ei = d_in[1];

    WPtrs wp;
    wp.W[0] = (const float*)d_in[2];  wp.W[1] = (const float*)d_in[4];
    wp.W[2] = (const float*)d_in[6];  wp.W[3] = (const float*)d_in[8];
    wp.W[4] = (const float*)d_in[10]; wp.W[5] = (const float*)d_in[12];
    wp.W[6] = (const float*)d_in[14]; wp.W[7] = (const float*)d_in[16];

    BiasPtrs b1, b2;
    b1.b[0] = (const float*)d_in[3];  b1.b[1] = (const float*)d_in[5];
    b1.b[2] = (const float*)d_in[7];  b1.b[3] = (const float*)d_in[9];
    b2.b[0] = (const float*)d_in[11]; b2.b[1] = (const float*)d_in[13];
    b2.b[2] = (const float*)d_in[15]; b2.b[3] = (const float*)d_in[17];

    const int node_grid = (NN + 255) / 256;
    const int edge_grid = (NE + 255) / 256;
    const dim3 gemm_grid((NN + 127) / 128, 4);
    const dim3 wprep_grid((C * C + 255) / 256, 8);
    const int attn_grid = (NN * 32 + 255) / 256;

    // ---- prep: dtype detect, weight transpose/convert, CSR build ----
    detect_kernel<<<1, 256>>>((const int*)ei);
    wprep_kernel<<<wprep_grid, 256>>>(wp);
    deg_zero_kernel<<<node_grid, 256>>>();
    hist_kernel<<<edge_grid, 256>>>(ei);
    scan1_kernel<<<NBLK, CHUNK>>>();
    scan2_kernel<<<1, 128>>>();
    scan3_kernel<<<node_grid, 256>>>();
    scatter_kernel<<<edge_grid, 256>>>(ei);

    // ---- layer 1 ----
    gemm4_tc<<<gemm_grid, 256>>>(x, b1, 0, 0);
    attn_kernel<<<attn_grid, 256>>>(nullptr, 1, 1);

    // ---- layer 2 ----
    gemm4_tc<<<gemm_grid, 256>>>(nullptr, b2, 1, 4);
    attn_kernel<<<attn_grid, 256>>>((float*)d_out, 0, 0);
}

// round 10
// speedup vs baseline: 1.0055x; 1.0055x over previous
#include <cuda_runtime.h>

// ---------------------------------------------------------------------------
// TemporalGNN: 2x TransformerConv(heads=1), N=100k nodes, E=800k edges, C=128.
// CSR-by-dst build + per-layer [tf32 tensor-core gemm4] -> [fused attention].
// R9 decomposition round: GEMM reverted to the proven R6 version (the R8
// register-prefetch variant is the prime regression suspect: +32 live regs
// -> 1 CTA/SM). Attention keeps the R7 8-lanes/edge x 4-edges/iter layout.
// ---------------------------------------------------------------------------

#define NN 100000
#define NE 800000
#define C  128
#define CHUNK 1024
#define NBLK ((NN + CHUNK - 1) / CHUNK)  // 98

__device__ float    g_q[NN * C];
__device__ float    g_k[NN * C];
__device__ float    g_v[NN * C];
__device__ float    g_s[NN * C];
__device__ float    g_h[NN * C];
__device__ unsigned g_wt[8 * C * C];   // all 8 weight mats, transposed, tf32 bits
__device__ int      g_deg[NN];
__device__ int      g_rptmp[NN + 1];
__device__ int      g_rowptr[NN + 1];
__device__ int      g_wpos[NN];
__device__ int      g_blocksums[NBLK];
__device__ int      g_blockoffs[NBLK];
__device__ int      g_srcs[NE];
__device__ int      g_is_i32;

struct WPtrs  { const float* W[8]; };
struct BiasPtrs { const float* b[4]; };

__device__ __forceinline__ unsigned f2tf32(float x) {
    unsigned u;
    asm("cvt.rna.tf32.f32 %0, %1;" : "=r"(u) : "f"(x));
    return u;
}

__device__ __forceinline__ void mma_tf32(float* c, const unsigned* a, const unsigned* b) {
    asm volatile(
        "mma.sync.aligned.m16n8k8.row.col.f32.tf32.tf32.f32 "
        "{%0,%1,%2,%3}, {%4,%5,%6,%7}, {%8,%9}, {%0,%1,%2,%3};"
        : "+f"(c[0]), "+f"(c[1]), "+f"(c[2]), "+f"(c[3])
        : "r"(a[0]), "r"(a[1]), "r"(a[2]), "r"(a[3]), "r"(b[0]), "r"(b[1]));
}

// ---------------------------------------------------------------------------
// edge_index dtype detection (int32 vs int64): int64 values < 2^31 have all
// odd 32-bit words zero.
// ---------------------------------------------------------------------------
__global__ void detect_kernel(const int* __restrict__ ei32) {
    __shared__ int found;
    if (threadIdx.x == 0) found = 0;
    __syncthreads();
    for (int i = threadIdx.x; i < 4096; i += blockDim.x)
        if (ei32[2 * i + 1] != 0) found = 1;
    __syncthreads();
    if (threadIdx.x == 0) g_is_i32 = found;
}

__device__ __forceinline__ int load_src(const void* ei, int e) {
    if (g_is_i32) return ((const int*)ei)[e];
    return (int)((const long long*)ei)[e];
}
__device__ __forceinline__ int load_dst(const void* ei, int e) {
    if (g_is_i32) return ((const int*)ei)[NE + e];
    return (int)((const long long*)ei)[NE + e];
}

// ---------------------------------------------------------------------------
// CSR build
// ---------------------------------------------------------------------------
__global__ void deg_zero_kernel() {
    int i = blockIdx.x * blockDim.x + threadIdx.x;
    if (i < NN) g_deg[i] = 0;
}

__global__ void hist_kernel(const void* __restrict__ ei) {
    int e = blockIdx.x * blockDim.x + threadIdx.x;
    if (e >= NE) return;
    int d = load_dst(ei, e);
    int s = load_src(ei, e);
    if ((unsigned)d < NN && (unsigned)s < NN) atomicAdd(&g_deg[d], 1);
}

__global__ __launch_bounds__(CHUNK) void scan1_kernel() {
    __shared__ int sh[CHUNK];
    int t = threadIdx.x;
    int i = blockIdx.x * CHUNK + t;
    int v = (i < NN) ? g_deg[i] : 0;
    sh[t] = v;
    __syncthreads();
#pragma unroll
    for (int off = 1; off < CHUNK; off <<= 1) {
        int add = (t >= off) ? sh[t - off] : 0;
        __syncthreads();
        sh[t] += add;
        __syncthreads();
    }
    if (i < NN) g_rptmp[i + 1] = sh[t];
    if (t == CHUNK - 1) g_blocksums[blockIdx.x] = sh[t];
}

__global__ __launch_bounds__(128) void scan2_kernel() {
    __shared__ int sh[128];
    int t = threadIdx.x;
    int v = (t < NBLK) ? g_blocksums[t] : 0;
    sh[t] = v;
    __syncthreads();
#pragma unroll
    for (int off = 1; off < 128; off <<= 1) {
        int add = (t >= off) ? sh[t - off] : 0;
        __syncthreads();
        sh[t] += add;
        __syncthreads();
    }
    if (t < NBLK) g_blockoffs[t] = sh[t] - v;
}

__global__ void scan3_kernel() {
    int i = blockIdx.x * blockDim.x + threadIdx.x;
    if (i >= NN) return;
    g_rowptr[i + 1] = g_rptmp[i + 1] + g_blockoffs[i >> 10];
    g_wpos[i] = (i == 0) ? 0 : g_rptmp[i] + g_blockoffs[(i - 1) >> 10];
    if (i == 0) g_rowptr[0] = 0;
}

__global__ void scatter_kernel(const void* __restrict__ ei) {
    int e = blockIdx.x * blockDim.x + threadIdx.x;
    if (e >= NE) return;
    int d = load_dst(ei, e);
    int s = load_src(ei, e);
    if ((unsigned)d >= NN || (unsigned)s >= NN) return;
    int pos = atomicAdd(&g_wpos[d], 1);
    g_srcs[pos] = s;
}

// ---------------------------------------------------------------------------
// Weight prep: transpose W[k][n] -> Wt[n][k] with round-to-nearest tf32.
// ---------------------------------------------------------------------------
__global__ void wprep_kernel(WPtrs wp) {
    int mat = blockIdx.y;
    int idx = blockIdx.x * blockDim.x + threadIdx.x;
    if (idx >= C * C) return;
    int k = idx >> 7;
    int n = idx & 127;
    g_wt[mat * C * C + n * C + k] = f2tf32(wp.W[mat][idx]);
}

// ---------------------------------------------------------------------------
// tf32 tensor-core GEMM (R6 version, proven 651us config):
// {g_q,g_k,g_v,g_s}[mat] = X @ W_mat + b_mat
// BM=128, BN=128, BK=32. 256 threads = 8 warps, warp tile 64x32.
// ---------------------------------------------------------------------------
__global__ __launch_bounds__(256) void gemm4_tc(const float* __restrict__ Xin,
                                                BiasPtrs bp, int use_h, int wt_base) {
    const int mat = blockIdx.y;
    const float* __restrict__ X = use_h ? g_h : Xin;
    const float* __restrict__ bias = bp.b[mat];
    float* outs[4] = {g_q, g_k, g_v, g_s};
    float* __restrict__ Y = outs[mat];
    const unsigned* __restrict__ Wt = &g_wt[(wt_base + mat) * C * C];

    __shared__ unsigned Xs[128][36];
    __shared__ unsigned Ws[128][36];

    const int tid = threadIdx.x;
    const int lane = tid & 31;
    const int wid = tid >> 5;
    const int warp_m = (wid & 1) * 64;
    const int warp_n = (wid >> 1) * 32;
    const int blockRow = blockIdx.x * 128;

    const int lrow = tid >> 1;
    const int lcol = (tid & 1) * 16;

    float acc[4][4][4];
#pragma unroll
    for (int mi = 0; mi < 4; mi++)
#pragma unroll
        for (int ni = 0; ni < 4; ni++)
#pragma unroll
            for (int r = 0; r < 4; r++) acc[mi][ni][r] = 0.0f;

    for (int k0 = 0; k0 < 128; k0 += 32) {
        const int gr = blockRow + lrow;
#pragma unroll
        for (int j = 0; j < 4; j++) {
            const int c = lcol + j * 4;
            float4 xv = make_float4(0.f, 0.f, 0.f, 0.f);
            if (gr < NN) xv = *(const float4*)&X[gr * 128 + k0 + c];
            uint4 uv;
            uv.x = f2tf32(xv.x); uv.y = f2tf32(xv.y);
            uv.z = f2tf32(xv.z); uv.w = f2tf32(xv.w);
            *(uint4*)&Xs[lrow][c] = uv;
            *(uint4*)&Ws[lrow][c] = *(const uint4*)&Wt[lrow * 128 + k0 + c];
        }
        __syncthreads();

#pragma unroll
        for (int kk = 0; kk < 32; kk += 8) {
            unsigned a[4][4], b[4][2];
#pragma unroll
            for (int mi = 0; mi < 4; mi++) {
                const int r = warp_m + mi * 16 + (lane >> 2);
                const int kc = kk + (lane & 3);
                a[mi][0] = Xs[r][kc];
                a[mi][1] = Xs[r + 8][kc];
                a[mi][2] = Xs[r][kc + 4];
                a[mi][3] = Xs[r + 8][kc + 4];
            }
#pragma unroll
            for (int ni = 0; ni < 4; ni++) {
                const int n = warp_n + ni * 8 + (lane >> 2);
                const int kc = kk + (lane & 3);
                b[ni][0] = Ws[n][kc];
                b[ni][1] = Ws[n][kc + 4];
            }
#pragma unroll
            for (int mi = 0; mi < 4; mi++)
#pragma unroll
                for (int ni = 0; ni < 4; ni++) mma_tf32(acc[mi][ni], a[mi], b[ni]);
        }
        __syncthreads();
    }

    float2 b2[4];
#pragma unroll
    for (int ni = 0; ni < 4; ni++)
        b2[ni] = *(const float2*)&bias[warp_n + ni * 8 + (lane & 3) * 2];

#pragma unroll
    for (int mi = 0; mi < 4; mi++) {
        const int row0 = blockRow + warp_m + mi * 16 + (lane >> 2);
        const int row1 = row0 + 8;
#pragma unroll
        for (int ni = 0; ni < 4; ni++) {
            const int col = warp_n + ni * 8 + (lane & 3) * 2;
            if (row0 < NN) {
                float2 r;
                r.x = acc[mi][ni][0] + b2[ni].x;
                r.y = acc[mi][ni][1] + b2[ni].y;
                *(float2*)&Y[row0 * 128 + col] = r;
            }
            if (row1 < NN) {
                float2 r;
                r.x = acc[mi][ni][2] + b2[ni].x;
                r.y = acc[mi][ni][3] + b2[ni].y;
                *(float2*)&Y[row1 * 128 + col] = r;
            }
        }
    }
}

// ---------------------------------------------------------------------------
// Fused attention (R7): one warp per dst node; 4 edge groups of 8 lanes.
// Group g handles edge base+g; sublane sl owns channels [16*sl, 16*sl+16).
//   p_partial = <q_sl, k_sl>;  3-level shfl (xor 1,2,4) sums within group.
//   w = exp(p/sqrt(128)) (0 for tail-invalid groups; their loads clamp to
//   src 0 -> L1-resident, ~free).
//   Final: xor 8,16 combines the 4 groups' esum/acc; g==0 lanes write
//   out = acc/esum + skip (+relu).
// ---------------------------------------------------------------------------
__global__ __launch_bounds__(256) void attn_kernel(float* __restrict__ outp,
                                                   int relu, int write_h) {
    const int node = (blockIdx.x * blockDim.x + threadIdx.x) >> 5;
    const int lane = threadIdx.x & 31;
    if (node >= NN) return;

    float* __restrict__ out = write_h ? g_h : outp;

    const int g  = lane >> 3;   // edge group 0..3
    const int sl = lane & 7;    // sublane: channels [16*sl, 16*sl+16)

    const int beg = g_rowptr[node];
    const int end = g_rowptr[node + 1];

    const float4* __restrict__ qrow = (const float4*)&g_q[node * C];
    float4 q0 = qrow[sl * 4 + 0];
    float4 q1 = qrow[sl * 4 + 1];
    float4 q2 = qrow[sl * 4 + 2];
    float4 q3 = qrow[sl * 4 + 3];

    float4 a0 = make_float4(0.f, 0.f, 0.f, 0.f);
    float4 a1 = a0, a2 = a0, a3 = a0;
    float esum = 0.f;

    for (int base = beg; base < end; base += 4) {
        const int ei = base + g;
        const bool valid = (ei < end);
        const int src = valid ? g_srcs[ei] : 0;

        const float4* __restrict__ krow = (const float4*)&g_k[src * C];
        const float4 k0 = krow[sl * 4 + 0];
        const float4 k1 = krow[sl * 4 + 1];
        const float4 k2 = krow[sl * 4 + 2];
        const float4 k3 = krow[sl * 4 + 3];
        const float4* __restrict__ vrow = (const float4*)&g_v[src * C];
        const float4 v0 = vrow[sl * 4 + 0];
        const float4 v1 = vrow[sl * 4 + 1];
        const float4 v2 = vrow[sl * 4 + 2];
        const float4 v3 = vrow[sl * 4 + 3];

        float p = q0.x * k0.x + q0.y * k0.y + q0.z * k0.z + q0.w * k0.w;
        p = fmaf(q1.x, k1.x, p); p = fmaf(q1.y, k1.y, p);
        p = fmaf(q1.z, k1.z, p); p = fmaf(q1.w, k1.w, p);
        p = fmaf(q2.x, k2.x, p); p = fmaf(q2.y, k2.y, p);
        p = fmaf(q2.z, k2.z, p); p = fmaf(q2.w, k2.w, p);
        p = fmaf(q3.x, k3.x, p); p = fmaf(q3.y, k3.y, p);
        p = fmaf(q3.z, k3.z, p); p = fmaf(q3.w, k3.w, p);

        // reduce within the 8-lane group (xor 1,2,4 stays inside the group)
        p += __shfl_xor_sync(0xFFFFFFFFu, p, 1);
        p += __shfl_xor_sync(0xFFFFFFFFu, p, 2);
        p += __shfl_xor_sync(0xFFFFFFFFu, p, 4);

        const float w = valid ? __expf(p * 0.08838834764831845f) : 0.f;
        esum += w;

        a0.x = fmaf(w, v0.x, a0.x); a0.y = fmaf(w, v0.y, a0.y);
        a0.z = fmaf(w, v0.z, a0.z); a0.w = fmaf(w, v0.w, a0.w);
        a1.x = fmaf(w, v1.x, a1.x); a1.y = fmaf(w, v1.y, a1.y);
        a1.z = fmaf(w, v1.z, a1.z); a1.w = fmaf(w, v1.w, a1.w);
        a2.x = fmaf(w, v2.x, a2.x); a2.y = fmaf(w, v2.y, a2.y);
        a2.z = fmaf(w, v2.z, a2.z); a2.w = fmaf(w, v2.w, a2.w);
        a3.x = fmaf(w, v3.x, a3.x); a3.y = fmaf(w, v3.y, a3.y);
        a3.z = fmaf(w, v3.z, a3.z); a3.w = fmaf(w, v3.w, a3.w);
    }

    // combine the 4 edge groups (xor 8, 16 flip the group bits)
#pragma unroll
    for (int off = 8; off <= 16; off <<= 1) {
        esum += __shfl_xor_sync(0xFFFFFFFFu, esum, off);
        a0.x += __shfl_xor_sync(0xFFFFFFFFu, a0.x, off);
        a0.y += __shfl_xor_sync(0xFFFFFFFFu, a0.y, off);
        a0.z += __shfl_xor_sync(0xFFFFFFFFu, a0.z, off);
        a0.w += __shfl_xor_sync(0xFFFFFFFFu, a0.w, off);
        a1.x += __shfl_xor_sync(0xFFFFFFFFu, a1.x, off);
        a1.y += __shfl_xor_sync(0xFFFFFFFFu, a1.y, off);
        a1.z += __shfl_xor_sync(0xFFFFFFFFu, a1.z, off);
        a1.w += __shfl_xor_sync(0xFFFFFFFFu, a1.w, off);
        a2.x += __shfl_xor_sync(0xFFFFFFFFu, a2.x, off);
        a2.y += __shfl_xor_sync(0xFFFFFFFFu, a2.y, off);
        a2.z += __shfl_xor_sync(0xFFFFFFFFu, a2.z, off);
        a2.w += __shfl_xor_sync(0xFFFFFFFFu, a2.w, off);
        a3.x += __shfl_xor_sync(0xFFFFFFFFu, a3.x, off);
        a3.y += __shfl_xor_sync(0xFFFFFFFFu, a3.y, off);
        a3.z += __shfl_xor_sync(0xFFFFFFFFu, a3.z, off);
        a3.w += __shfl_xor_sync(0xFFFFFFFFu, a3.w, off);
    }

    if (g == 0) {
        const float inv = (esum > 0.f) ? (1.0f / esum) : 0.f;
        const int base = node * C + sl * 16;
        const float4* __restrict__ srow = (const float4*)&g_s[base];
        float4 av[4] = {a0, a1, a2, a3};
#pragma unroll
        for (int j = 0; j < 4; j++) {
            const float4 s4 = srow[j];
            float4 r;
            r.x = fmaf(av[j].x, inv, s4.x);
            r.y = fmaf(av[j].y, inv, s4.y);
            r.z = fmaf(av[j].z, inv, s4.z);
            r.w = fmaf(av[j].w, inv, s4.w);
            if (relu) {
                r.x = fmaxf(r.x, 0.f); r.y = fmaxf(r.y, 0.f);
                r.z = fmaxf(r.z, 0.f); r.w = fmaxf(r.w, 0.f);
            }
            *(float4*)&out[base + j * 4] = r;
        }
    }
}

// ---------------------------------------------------------------------------
// Launch (pure kernel launches — graph-capture safe)
// ---------------------------------------------------------------------------
extern "C" void kernel_launch(void* const* d_in, const int* in_sizes, int n_in,
                              void* d_out, int out_size) {
    const float* x = (const float*)d_in[0];
    const void* ei = d_in[1];

    WPtrs wp;
    wp.W[0] = (const float*)d_in[2];  wp.W[1] = (const float*)d_in[4];
    wp.W[2] = (const float*)d_in[6];  wp.W[3] = (const float*)d_in[8];
    wp.W[4] = (const float*)d_in[10]; wp.W[5] = (const float*)d_in[12];
    wp.W[6] = (const float*)d_in[14]; wp.W[7] = (const float*)d_in[16];

    BiasPtrs b1, b2;
    b1.b[0] = (const float*)d_in[3];  b1.b[1] = (const float*)d_in[5];
    b1.b[2] = (const float*)d_in[7];  b1.b[3] = (const float*)d_in[9];
    b2.b[0] = (const float*)d_in[11]; b2.b[1] = (const float*)d_in[13];
    b2.b[2] = (const float*)d_in[15]; b2.b[3] = (const float*)d_in[17];

    const int node_grid = (NN + 255) / 256;
    const int edge_grid = (NE + 255) / 256;
    const dim3 gemm_grid((NN + 127) / 128, 4);
    const dim3 wprep_grid((C * C + 255) / 256, 8);
    const int attn_grid = (NN * 32 + 255) / 256;

    // ---- prep: dtype detect, weight transpose/convert, CSR build ----
    detect_kernel<<<1, 256>>>((const int*)ei);
    wprep_kernel<<<wprep_grid, 256>>>(wp);
    deg_zero_kernel<<<node_grid, 256>>>();
    hist_kernel<<<edge_grid, 256>>>(ei);
    scan1_kernel<<<NBLK, CHUNK>>>();
    scan2_kernel<<<1, 128>>>();
    scan3_kernel<<<node_grid, 256>>>();
    scatter_kernel<<<edge_grid, 256>>>(ei);

    // ---- layer 1 ----
    gemm4_tc<<<gemm_grid, 256>>>(x, b1, 0, 0);
    attn_kernel<<<attn_grid, 256>>>(nullptr, 1, 1);

    // ---- layer 2 ----
    gemm4_tc<<<gemm_grid, 256>>>(nullptr, b2, 1, 4);
    attn_kernel<<<attn_grid, 256>>>((float*)d_out, 0, 0);
}

// round 11
// speedup vs baseline: 1.2031x; 1.1966x over previous
#include <cuda_runtime.h>

// ---------------------------------------------------------------------------
// TemporalGNN: 2x TransformerConv(heads=1), N=100k nodes, E=800k edges, C=128.
// CSR-by-dst build + per-layer [tf32 tensor-core gemm4] -> [fused attention].
// R10: attention = R6 coalesced full-row loads (the proven memory pattern;
// R7's 8-lane groups doubled L1 wavefronts and regressed +94us) + paired
// 2-edge butterfly reduction (5 shfl + 1 expf per TWO edges, MLP 4).
// ---------------------------------------------------------------------------

#define NN 100000
#define NE 800000
#define C  128
#define CHUNK 1024
#define NBLK ((NN + CHUNK - 1) / CHUNK)  // 98

__device__ float    g_q[NN * C];
__device__ float    g_k[NN * C];
__device__ float    g_v[NN * C];
__device__ float    g_s[NN * C];
__device__ float    g_h[NN * C];
__device__ unsigned g_wt[8 * C * C];   // all 8 weight mats, transposed, tf32 bits
__device__ int      g_deg[NN];
__device__ int      g_rptmp[NN + 1];
__device__ int      g_rowptr[NN + 1];
__device__ int      g_wpos[NN];
__device__ int      g_blocksums[NBLK];
__device__ int      g_blockoffs[NBLK];
__device__ int      g_srcs[NE];
__device__ int      g_is_i32;

struct WPtrs  { const float* W[8]; };
struct BiasPtrs { const float* b[4]; };

__device__ __forceinline__ unsigned f2tf32(float x) {
    unsigned u;
    asm("cvt.rna.tf32.f32 %0, %1;" : "=r"(u) : "f"(x));
    return u;
}

__device__ __forceinline__ void mma_tf32(float* c, const unsigned* a, const unsigned* b) {
    asm volatile(
        "mma.sync.aligned.m16n8k8.row.col.f32.tf32.tf32.f32 "
        "{%0,%1,%2,%3}, {%4,%5,%6,%7}, {%8,%9}, {%0,%1,%2,%3};"
        : "+f"(c[0]), "+f"(c[1]), "+f"(c[2]), "+f"(c[3])
        : "r"(a[0]), "r"(a[1]), "r"(a[2]), "r"(a[3]), "r"(b[0]), "r"(b[1]));
}

// ---------------------------------------------------------------------------
// edge_index dtype detection (int32 vs int64): int64 values < 2^31 have all
// odd 32-bit words zero.
// ---------------------------------------------------------------------------
__global__ void detect_kernel(const int* __restrict__ ei32) {
    __shared__ int found;
    if (threadIdx.x == 0) found = 0;
    __syncthreads();
    for (int i = threadIdx.x; i < 4096; i += blockDim.x)
        if (ei32[2 * i + 1] != 0) found = 1;
    __syncthreads();
    if (threadIdx.x == 0) g_is_i32 = found;
}

__device__ __forceinline__ int load_src(const void* ei, int e) {
    if (g_is_i32) return ((const int*)ei)[e];
    return (int)((const long long*)ei)[e];
}
__device__ __forceinline__ int load_dst(const void* ei, int e) {
    if (g_is_i32) return ((const int*)ei)[NE + e];
    return (int)((const long long*)ei)[NE + e];
}

// ---------------------------------------------------------------------------
// CSR build
// ---------------------------------------------------------------------------
__global__ void deg_zero_kernel() {
    int i = blockIdx.x * blockDim.x + threadIdx.x;
    if (i < NN) g_deg[i] = 0;
}

__global__ void hist_kernel(const void* __restrict__ ei) {
    int e = blockIdx.x * blockDim.x + threadIdx.x;
    if (e >= NE) return;
    int d = load_dst(ei, e);
    int s = load_src(ei, e);
    if ((unsigned)d < NN && (unsigned)s < NN) atomicAdd(&g_deg[d], 1);
}

__global__ __launch_bounds__(CHUNK) void scan1_kernel() {
    __shared__ int sh[CHUNK];
    int t = threadIdx.x;
    int i = blockIdx.x * CHUNK + t;
    int v = (i < NN) ? g_deg[i] : 0;
    sh[t] = v;
    __syncthreads();
#pragma unroll
    for (int off = 1; off < CHUNK; off <<= 1) {
        int add = (t >= off) ? sh[t - off] : 0;
        __syncthreads();
        sh[t] += add;
        __syncthreads();
    }
    if (i < NN) g_rptmp[i + 1] = sh[t];
    if (t == CHUNK - 1) g_blocksums[blockIdx.x] = sh[t];
}

__global__ __launch_bounds__(128) void scan2_kernel() {
    __shared__ int sh[128];
    int t = threadIdx.x;
    int v = (t < NBLK) ? g_blocksums[t] : 0;
    sh[t] = v;
    __syncthreads();
#pragma unroll
    for (int off = 1; off < 128; off <<= 1) {
        int add = (t >= off) ? sh[t - off] : 0;
        __syncthreads();
        sh[t] += add;
        __syncthreads();
    }
    if (t < NBLK) g_blockoffs[t] = sh[t] - v;
}

__global__ void scan3_kernel() {
    int i = blockIdx.x * blockDim.x + threadIdx.x;
    if (i >= NN) return;
    g_rowptr[i + 1] = g_rptmp[i + 1] + g_blockoffs[i >> 10];
    g_wpos[i] = (i == 0) ? 0 : g_rptmp[i] + g_blockoffs[(i - 1) >> 10];
    if (i == 0) g_rowptr[0] = 0;
}

__global__ void scatter_kernel(const void* __restrict__ ei) {
    int e = blockIdx.x * blockDim.x + threadIdx.x;
    if (e >= NE) return;
    int d = load_dst(ei, e);
    int s = load_src(ei, e);
    if ((unsigned)d >= NN || (unsigned)s >= NN) return;
    int pos = atomicAdd(&g_wpos[d], 1);
    g_srcs[pos] = s;
}

// ---------------------------------------------------------------------------
// Weight prep: transpose W[k][n] -> Wt[n][k] with round-to-nearest tf32.
// ---------------------------------------------------------------------------
__global__ void wprep_kernel(WPtrs wp) {
    int mat = blockIdx.y;
    int idx = blockIdx.x * blockDim.x + threadIdx.x;
    if (idx >= C * C) return;
    int k = idx >> 7;
    int n = idx & 127;
    g_wt[mat * C * C + n * C + k] = f2tf32(wp.W[mat][idx]);
}

// ---------------------------------------------------------------------------
// tf32 tensor-core GEMM (R6 version, proven 651us config):
// {g_q,g_k,g_v,g_s}[mat] = X @ W_mat + b_mat
// BM=128, BN=128, BK=32. 256 threads = 8 warps, warp tile 64x32.
// ---------------------------------------------------------------------------
__global__ __launch_bounds__(256) void gemm4_tc(const float* __restrict__ Xin,
                                                BiasPtrs bp, int use_h, int wt_base) {
    const int mat = blockIdx.y;
    const float* __restrict__ X = use_h ? g_h : Xin;
    const float* __restrict__ bias = bp.b[mat];
    float* outs[4] = {g_q, g_k, g_v, g_s};
    float* __restrict__ Y = outs[mat];
    const unsigned* __restrict__ Wt = &g_wt[(wt_base + mat) * C * C];

    __shared__ unsigned Xs[128][36];
    __shared__ unsigned Ws[128][36];

    const int tid = threadIdx.x;
    const int lane = tid & 31;
    const int wid = tid >> 5;
    const int warp_m = (wid & 1) * 64;
    const int warp_n = (wid >> 1) * 32;
    const int blockRow = blockIdx.x * 128;

    const int lrow = tid >> 1;
    const int lcol = (tid & 1) * 16;

    float acc[4][4][4];
#pragma unroll
    for (int mi = 0; mi < 4; mi++)
#pragma unroll
        for (int ni = 0; ni < 4; ni++)
#pragma unroll
            for (int r = 0; r < 4; r++) acc[mi][ni][r] = 0.0f;

    for (int k0 = 0; k0 < 128; k0 += 32) {
        const int gr = blockRow + lrow;
#pragma unroll
        for (int j = 0; j < 4; j++) {
            const int c = lcol + j * 4;
            float4 xv = make_float4(0.f, 0.f, 0.f, 0.f);
            if (gr < NN) xv = *(const float4*)&X[gr * 128 + k0 + c];
            uint4 uv;
            uv.x = f2tf32(xv.x); uv.y = f2tf32(xv.y);
            uv.z = f2tf32(xv.z); uv.w = f2tf32(xv.w);
            *(uint4*)&Xs[lrow][c] = uv;
            *(uint4*)&Ws[lrow][c] = *(const uint4*)&Wt[lrow * 128 + k0 + c];
        }
        __syncthreads();

#pragma unroll
        for (int kk = 0; kk < 32; kk += 8) {
            unsigned a[4][4], b[4][2];
#pragma unroll
            for (int mi = 0; mi < 4; mi++) {
                const int r = warp_m + mi * 16 + (lane >> 2);
                const int kc = kk + (lane & 3);
                a[mi][0] = Xs[r][kc];
                a[mi][1] = Xs[r + 8][kc];
                a[mi][2] = Xs[r][kc + 4];
                a[mi][3] = Xs[r + 8][kc + 4];
            }
#pragma unroll
            for (int ni = 0; ni < 4; ni++) {
                const int n = warp_n + ni * 8 + (lane >> 2);
                const int kc = kk + (lane & 3);
                b[ni][0] = Ws[n][kc];
                b[ni][1] = Ws[n][kc + 4];
            }
#pragma unroll
            for (int mi = 0; mi < 4; mi++)
#pragma unroll
                for (int ni = 0; ni < 4; ni++) mma_tf32(acc[mi][ni], a[mi], b[ni]);
        }
        __syncthreads();
    }

    float2 b2[4];
#pragma unroll
    for (int ni = 0; ni < 4; ni++)
        b2[ni] = *(const float2*)&bias[warp_n + ni * 8 + (lane & 3) * 2];

#pragma unroll
    for (int mi = 0; mi < 4; mi++) {
        const int row0 = blockRow + warp_m + mi * 16 + (lane >> 2);
        const int row1 = row0 + 8;
#pragma unroll
        for (int ni = 0; ni < 4; ni++) {
            const int col = warp_n + ni * 8 + (lane & 3) * 2;
            if (row0 < NN) {
                float2 r;
                r.x = acc[mi][ni][0] + b2[ni].x;
                r.y = acc[mi][ni][1] + b2[ni].y;
                *(float2*)&Y[row0 * 128 + col] = r;
            }
            if (row1 < NN) {
                float2 r;
                r.x = acc[mi][ni][2] + b2[ni].x;
                r.y = acc[mi][ni][3] + b2[ni].y;
                *(float2*)&Y[row1 * 128 + col] = r;
            }
        }
    }
}

// ---------------------------------------------------------------------------
// Fused attention (R10): one warp per dst node, fully-coalesced full-row
// loads (as in the 651us baseline), TWO edges per iteration with a paired
// butterfly reduction:
//   fold: z = (lane<16)?p0:p1;  z += shfl_xor((lane<16)?p1:p0, 16)
//   then xor 8,4,2,1 -> lanes 0-15 hold sum(p0), lanes 16-31 sum(p1);
//   ONE expf evaluates both edges' weights; 2 broadcasts feed the dual FMA.
// Odd tail: src1 clamps to src0 (L1 hit), w1 forced to 0.
// ---------------------------------------------------------------------------
__global__ __launch_bounds__(256) void attn_kernel(float* __restrict__ outp,
                                                   int relu, int write_h) {
    const int node = (blockIdx.x * blockDim.x + threadIdx.x) >> 5;
    const int lane = threadIdx.x & 31;
    if (node >= NN) return;

    float* __restrict__ out = write_h ? g_h : outp;

    const int beg = g_rowptr[node];
    const int end = g_rowptr[node + 1];

    const float4 q4 = ((const float4*)&g_q[node * C])[lane];
    const bool lowhalf = (lane < 16);

    float ax = 0.f, ay = 0.f, az = 0.f, aw = 0.f;
    float esum = 0.f;

    for (int base = beg; base < end; base += 2) {
        const int src0 = g_srcs[base];
        const bool has1 = (base + 1 < end);
        const int src1 = has1 ? g_srcs[base + 1] : src0;

        const float4 k0 = ((const float4*)&g_k[src0 * C])[lane];
        const float4 k1 = ((const float4*)&g_k[src1 * C])[lane];
        const float4 v0 = ((const float4*)&g_v[src0 * C])[lane];
        const float4 v1 = ((const float4*)&g_v[src1 * C])[lane];

        float p0 = q4.x * k0.x + q4.y * k0.y + q4.z * k0.z + q4.w * k0.w;
        float p1 = q4.x * k1.x + q4.y * k1.y + q4.z * k1.z + q4.w * k1.w;

        // paired fold: lower half reduces edge0, upper half edge1
        float z = lowhalf ? p0 : p1;
        z += __shfl_xor_sync(0xFFFFFFFFu, lowhalf ? p1 : p0, 16);
        z += __shfl_xor_sync(0xFFFFFFFFu, z, 8);
        z += __shfl_xor_sync(0xFFFFFFFFu, z, 4);
        z += __shfl_xor_sync(0xFFFFFFFFu, z, 2);
        z += __shfl_xor_sync(0xFFFFFFFFu, z, 1);

        const float wz = __expf(z * 0.08838834764831845f);  // 1/sqrt(128)
        const float w0 = __shfl_sync(0xFFFFFFFFu, wz, 0);
        const float w1 = has1 ? __shfl_sync(0xFFFFFFFFu, wz, 16) : 0.f;
        esum += w0 + w1;

        ax = fmaf(w0, v0.x, fmaf(w1, v1.x, ax));
        ay = fmaf(w0, v0.y, fmaf(w1, v1.y, ay));
        az = fmaf(w0, v0.z, fmaf(w1, v1.z, az));
        aw = fmaf(w0, v0.w, fmaf(w1, v1.w, aw));
    }

    const float inv = (esum > 0.0f) ? (1.0f / esum) : 0.0f;
    const float4 s4 = ((const float4*)&g_s[node * C])[lane];
    float4 r;
    r.x = fmaf(ax, inv, s4.x);
    r.y = fmaf(ay, inv, s4.y);
    r.z = fmaf(az, inv, s4.z);
    r.w = fmaf(aw, inv, s4.w);
    if (relu) {
        r.x = fmaxf(r.x, 0.0f);
        r.y = fmaxf(r.y, 0.0f);
        r.z = fmaxf(r.z, 0.0f);
        r.w = fmaxf(r.w, 0.0f);
    }
    *(float4*)&out[node * C + lane * 4] = r;
}

// ---------------------------------------------------------------------------
// Launch (pure kernel launches — graph-capture safe)
// ---------------------------------------------------------------------------
extern "C" void kernel_launch(void* const* d_in, const int* in_sizes, int n_in,
                              void* d_out, int out_size) {
    const float* x = (const float*)d_in[0];
    const void* ei = d_in[1];

    WPtrs wp;
    wp.W[0] = (const float*)d_in[2];  wp.W[1] = (const float*)d_in[4];
    wp.W[2] = (const float*)d_in[6];  wp.W[3] = (const float*)d_in[8];
    wp.W[4] = (const float*)d_in[10]; wp.W[5] = (const float*)d_in[12];
    wp.W[6] = (const float*)d_in[14]; wp.W[7] = (const float*)d_in[16];

    BiasPtrs b1, b2;
    b1.b[0] = (const float*)d_in[3];  b1.b[1] = (const float*)d_in[5];
    b1.b[2] = (const float*)d_in[7];  b1.b[3] = (const float*)d_in[9];
    b2.b[0] = (const float*)d_in[11]; b2.b[1] = (const float*)d_in[13];
    b2.b[2] = (const float*)d_in[15]; b2.b[3] = (const float*)d_in[17];

    const int node_grid = (NN + 255) / 256;
    const int edge_grid = (NE + 255) / 256;
    const dim3 gemm_grid((NN + 127) / 128, 4);
    const dim3 wprep_grid((C * C + 255) / 256, 8);
    const int attn_grid = (NN * 32 + 255) / 256;

    // ---- prep: dtype detect, weight transpose/convert, CSR build ----
    detect_kernel<<<1, 256>>>((const int*)ei);
    wprep_kernel<<<wprep_grid, 256>>>(wp);
    deg_zero_kernel<<<node_grid, 256>>>();
    hist_kernel<<<edge_grid, 256>>>(ei);
    scan1_kernel<<<NBLK, CHUNK>>>();
    scan2_kernel<<<1, 128>>>();
    scan3_kernel<<<node_grid, 256>>>();
    scatter_kernel<<<edge_grid, 256>>>(ei);

    // ---- layer 1 ----
    gemm4_tc<<<gemm_grid, 256>>>(x, b1, 0, 0);
    attn_kernel<<<attn_grid, 256>>>(nullptr, 1, 1);

    // ---- layer 2 ----
    gemm4_tc<<<gemm_grid, 256>>>(nullptr, b2, 1, 4);
    attn_kernel<<<attn_grid, 256>>>((float*)d_out, 0, 0);
}